// round 12
// baseline (speedup 1.0000x reference)
#include <cuda_runtime.h>
#include <cuda_fp16.h>
#include <cuda_bf16.h>

#define N_USERS  100000
#define N_ITEMS  50000
#define N_TOPICS 1000
#define N_NODES  (N_USERS + N_ITEMS + N_TOPICS)   // 151000
#define DIM      64
#define NNZ      4000000
#define BATCH    16384

#define H2_PER_ROW    (DIM / 2)                   // 32 __half2 per node row
#define U4_PER_ROW    (DIM / 8)                   // 8 uint4 (16B) per fp16 row
#define TOTAL_H2      (N_NODES * H2_PER_ROW)
#define PAD           96                          // bucket capacity per node
#define COL_BITS      18
#define COL_MASK      ((1u << COL_BITS) - 1u)     // 151000 < 2^18
#define VAL_SCALE     16384.0f                    // 14-bit fixed-point val
#define LIST_CAP      (2 * BATCH)                 // max distinct gather nodes

// Layer buffers in fp16 (19.4 MB each)
__device__ __half2 g_E0[TOTAL_H2];
__device__ __half2 g_L1[TOTAL_H2];
__device__ __half2 g_L2[TOTAL_H2];
__device__ __half2 g_L3[TOTAL_H2];
// Padded edge buckets, one u32/edge: col [0:18), val fixed-point [18:32)
__device__ int          g_cnt[N_NODES];
__device__ unsigned int g_edges[(size_t)N_NODES * PAD];
// L3 node compaction
__device__ int g_need[N_NODES];
__device__ int g_list[LIST_CAP];
__device__ int g_nlist;

// Mixed-precision FMA: f16 * f16 + f32 -> f32 (sm_100+, PTX ISA 8.6).
// Product is exact in f32 (11x11-bit mantissas), accumulation in f32:
// numerically identical to cvt-to-f32 + FFMA, but no F2F instructions.
__device__ __forceinline__ float ffma_h(float acc, __half a, __half b) {
    unsigned short ua = __half_as_ushort(a);
    unsigned short ub = __half_as_ushort(b);
    float d;
    asm("fma.rn.f32.f16 %0, %1, %2, %3;" : "=f"(d) : "h"(ua), "h"(ub), "f"(acc));
    return d;
}

// ---------------------------------------------------------------------------
// init: E0 = fp16(concat); zero cnt, need flags, list counter
// ---------------------------------------------------------------------------
__global__ void init_kernel(const float2* __restrict__ user_w,
                            const float2* __restrict__ item_w,
                            const float2* __restrict__ topic_w) {
    int i = blockIdx.x * blockDim.x + threadIdx.x;
    if (i < N_NODES) { g_cnt[i] = 0; g_need[i] = 0; }
    if (i == 0) g_nlist = 0;
    if (i >= TOTAL_H2) return;
    int node  = i / H2_PER_ROW;
    int chunk = i % H2_PER_ROW;
    float2 v;
    if (node < N_USERS)                 v = user_w[node * H2_PER_ROW + chunk];
    else if (node < N_USERS + N_ITEMS)  v = item_w[(node - N_USERS) * H2_PER_ROW + chunk];
    else                                v = topic_w[(node - N_USERS - N_ITEMS) * H2_PER_ROW + chunk];
    g_E0[i] = __float22half2_rn(v);
}

// ---------------------------------------------------------------------------
// mark + compact the nodes the final gather will read (users, N_USERS+items)
// ---------------------------------------------------------------------------
__global__ void mark_kernel(const int* __restrict__ users,
                            const int* __restrict__ items) {
    int t = blockIdx.x * blockDim.x + threadIdx.x;
    if (t >= 2 * BATCH) return;
    int node = (t < BATCH) ? users[t] : (N_USERS + items[t - BATCH]);
    if (atomicExch(&g_need[node], 1) == 0) {
        int p = atomicAdd(&g_nlist, 1);
        g_list[p] = node;
    }
}

// ---------------------------------------------------------------------------
// scatter: bucket[r][slot++] = col | (q14(val) << 18)
// ---------------------------------------------------------------------------
__global__ void scatter_kernel(const int* __restrict__ row,
                               const int* __restrict__ col,
                               const float* __restrict__ vals) {
    int e = blockIdx.x * blockDim.x + threadIdx.x;
    if (e >= NNZ) return;
    int r = row[e];
    unsigned q = (unsigned)(vals[e] * VAL_SCALE + 0.5f);
    if (q > 16383u) q = 16383u;
    unsigned packed = ((unsigned)col[e]) | (q << COL_BITS);
    int slot = atomicAdd(&g_cnt[r], 1);
    g_edges[(size_t)r * PAD + slot] = packed;
}

// ---------------------------------------------------------------------------
// Bucket SpMM, edge-parallel (lane = g*8+l), packed edges, mixed f16->f32 FMA.
// Per step: 1 SHFL + AND/SHR + 1 cvt(u16->f16) + 1 LDG.128 + 8 HFMA(f32 acc).
// v stays an unscaled integer in f16 (<=16383, rel rounding 2^-12);
// the 1/16384 dequant scale is applied once in the epilogue.
// list==null: full pass over N_NODES rows; list!=null: only g_nlist rows.
// ---------------------------------------------------------------------------
__global__ void spmm_kernel(const uint4* __restrict__ xin,
                            uint4* __restrict__ yout,
                            const int* __restrict__ list) {
    int id   = (blockIdx.x * blockDim.x + threadIdx.x) >> 5;
    int lane = threadIdx.x & 31;
    int w;
    if (list) {
        if (id >= g_nlist) return;
        w = list[id];
    } else {
        if (id >= N_NODES) return;
        w = id;
    }

    int g = lane >> 3;      // edge group
    int l = lane & 7;       // 16B column slice

    int end = g_cnt[w];
    const unsigned* bucket = g_edges + (size_t)w * PAD;

    float acc[8];
    #pragma unroll
    for (int k = 0; k < 8; k++) acc[k] = 0.f;

    for (int e0 = 0; e0 < end; e0 += 32) {
        int      idx = e0 + lane;
        unsigned ed  = (idx < end) ? bucket[idx] : 0u;   // col=0, v=0
        int      n   = end - e0;                          // warp-uniform

        #pragma unroll
        for (int j = 0; j < 32; j += 4) {
            if (j >= n) break;                            // warp-uniform
            unsigned e = __shfl_sync(0xffffffffu, ed, j + g);
            int    c  = (int)(e & COL_MASK);
            __half vh = __ushort2half_rn((unsigned short)(e >> COL_BITS));
            uint4 x = xin[c * U4_PER_ROW + l];
            __half2 p0 = *(const __half2*)&x.x;
            __half2 p1 = *(const __half2*)&x.y;
            __half2 p2 = *(const __half2*)&x.z;
            __half2 p3 = *(const __half2*)&x.w;
            acc[0] = ffma_h(acc[0], __low2half(p0),  vh);
            acc[1] = ffma_h(acc[1], __high2half(p0), vh);
            acc[2] = ffma_h(acc[2], __low2half(p1),  vh);
            acc[3] = ffma_h(acc[3], __high2half(p1), vh);
            acc[4] = ffma_h(acc[4], __low2half(p2),  vh);
            acc[5] = ffma_h(acc[5], __high2half(p2), vh);
            acc[6] = ffma_h(acc[6], __low2half(p3),  vh);
            acc[7] = ffma_h(acc[7], __high2half(p3), vh);
        }
    }

    // reduce across the 4 edge groups (lanes l, l+8, l+16, l+24)
    #pragma unroll
    for (int k = 0; k < 8; k++) {
        acc[k] += __shfl_xor_sync(0xffffffffu, acc[k], 8);
        acc[k] += __shfl_xor_sync(0xffffffffu, acc[k], 16);
    }

    if (g == 0) {
        const float s = 1.0f / VAL_SCALE;
        __half2 h0 = __floats2half2_rn(acc[0] * s, acc[1] * s);
        __half2 h1 = __floats2half2_rn(acc[2] * s, acc[3] * s);
        __half2 h2 = __floats2half2_rn(acc[4] * s, acc[5] * s);
        __half2 h3 = __floats2half2_rn(acc[6] * s, acc[7] * s);
        uint4 o;
        o.x = *(const unsigned*)&h0;
        o.y = *(const unsigned*)&h1;
        o.z = *(const unsigned*)&h2;
        o.w = *(const unsigned*)&h3;
        yout[w * U4_PER_ROW + l] = o;
    }
}

// ---------------------------------------------------------------------------
// gather: out[b] = dot(sum4(u-row), sum4(i-row)) / 16   (fp32 math)
// ---------------------------------------------------------------------------
__global__ void gather_kernel(const int* __restrict__ users,
                              const int* __restrict__ items,
                              float* __restrict__ out) {
    int warp = (blockIdx.x * blockDim.x + threadIdx.x) >> 5;
    int lane = threadIdx.x & 31;
    if (warp >= BATCH) return;

    int u  = __ldg(users + warp);
    int it = N_USERS + __ldg(items + warp);

    int uo = u  * H2_PER_ROW + lane;
    int io = it * H2_PER_ROW + lane;

    float2 u0 = __half22float2(g_E0[uo]);
    float2 u1 = __half22float2(g_L1[uo]);
    float2 u2 = __half22float2(g_L2[uo]);
    float2 u3 = __half22float2(g_L3[uo]);
    float2 i0 = __half22float2(g_E0[io]);
    float2 i1 = __half22float2(g_L1[io]);
    float2 i2 = __half22float2(g_L2[io]);
    float2 i3 = __half22float2(g_L3[io]);

    float sux = (u0.x + u1.x) + (u2.x + u3.x);
    float suy = (u0.y + u1.y) + (u2.y + u3.y);
    float six = (i0.x + i1.x) + (i2.x + i3.x);
    float siy = (i0.y + i1.y) + (i2.y + i3.y);

    float s = sux * six + suy * siy;
    #pragma unroll
    for (int o = 16; o > 0; o >>= 1)
        s += __shfl_xor_sync(0xffffffffu, s, o);

    if (lane == 0) out[warp] = s * (1.0f / 16.0f);
}

// ---------------------------------------------------------------------------
extern "C" void kernel_launch(void* const* d_in, const int* in_sizes, int n_in,
                              void* d_out, int out_size) {
    const float2* user_w  = (const float2*)d_in[0];
    const float2* item_w  = (const float2*)d_in[1];
    const float2* topic_w = (const float2*)d_in[2];
    const float*  vals    = (const float*)d_in[3];
    const int*    row     = (const int*)d_in[4];
    const int*    col     = (const int*)d_in[5];
    const int*    users   = (const int*)d_in[6];
    const int*    items   = (const int*)d_in[7];
    float*        out     = (float*)d_out;

    void *E0, *L1b, *L2b, *L3b, *LIST;
    cudaGetSymbolAddress(&E0,  g_E0);
    cudaGetSymbolAddress(&L1b, g_L1);
    cudaGetSymbolAddress(&L2b, g_L2);
    cudaGetSymbolAddress(&L3b, g_L3);
    cudaGetSymbolAddress(&LIST, g_list);

    const int T = 256;
    const int eblocks = (TOTAL_H2 + T - 1) / T;
    const int nblocks = (NNZ + T - 1) / T;
    const int wblocks = (N_NODES * 32 + T - 1) / T;
    const int lblocks = (LIST_CAP * 32 + T - 1) / T;
    const int mblocks = (2 * BATCH + T - 1) / T;

    // init (E0 fp16 concat; zero cnt/need/nlist)
    init_kernel<<<eblocks, T>>>(user_w, item_w, topic_w);
    // mark+compact output node set; packed bucket scatter
    mark_kernel<<<mblocks, T>>>(users, items);
    scatter_kernel<<<nblocks, T>>>(row, col, vals);
    // layers 1,2 full; layer 3 only over the ~29K gathered nodes
    spmm_kernel<<<wblocks, T>>>((const uint4*)E0,  (uint4*)L1b, nullptr);
    spmm_kernel<<<wblocks, T>>>((const uint4*)L1b, (uint4*)L2b, nullptr);
    spmm_kernel<<<lblocks, T>>>((const uint4*)L2b, (uint4*)L3b, (const int*)LIST);
    // batched dots over sum of 4 layer buffers
    const int gblocks = (BATCH * 32 + T - 1) / T;
    gather_kernel<<<gblocks, T>>>(users, items, out);
}